// round 15
// baseline (speedup 1.0000x reference)
#include <cuda_runtime.h>
#include <cuda_bf16.h>
#include <math.h>

#define NNODES 4096
#define NCH    128
#define NELEM  10
#define NFEAT  128
#define NN16   (NNODES / 16)   // 256

// W fragments (mma.m16n8k16 bf16, 2-way split), built by wfrag_kernel:
//  g_Wb[wsel][sp][pair][kk16][lane] = uint4 {b0_t,b1_t,b0_t',b1_t'}
//  tcol t = 2*pair (+1 for t'), b0 = W[k0+2qc..+1][t*8+qr], b1 = k+8.
__device__ uint4 g_Wb[2 * 2 * 8 * 8 * 32];      // 128 KB

// ===========================================================================
// Compile-time real Clebsch-Gordan coefficients (e3nn convention).
// ===========================================================================
__host__ __device__ constexpr double cfact(int n) {
  double r = 1.0;
  for (int i = 2; i <= n; i++) r *= (double)i;
  return r;
}
__host__ __device__ constexpr double csqrt(double x) {
  if (x <= 0.0) return 0.0;
  double g = x > 1.0 ? x : 1.0;
  for (int i = 0; i < 64; i++) g = 0.5 * (g + x / g);
  return g;
}
__host__ __device__ constexpr double su2cg_ct(int j1,int m1,int j2,int m2,int j3,int m3) {
  if (m1 + m2 != m3) return 0.0;
  int vmin = -j1 + j2 + m3; if (-j1 + m1 > vmin) vmin = -j1 + m1; if (0 > vmin) vmin = 0;
  int vmax = j2 + j3 + m1; if (j3 - j1 + j2 < vmax) vmax = j3 - j1 + j2; if (j3 + m3 < vmax) vmax = j3 + m3;
  if (vmax < vmin) return 0.0;
  double C = csqrt((2.0*j3 + 1.0) * cfact(j3+j1-j2) * cfact(j3-j1+j2) * cfact(j1+j2-j3)
                   * cfact(j3+m3) * cfact(j3-m3)
                   / (cfact(j1+j2+j3+1) * cfact(j1-m1) * cfact(j1+m1)
                      * cfact(j2-m2) * cfact(j2+m2)));
  double S = 0.0;
  for (int v = vmin; v <= vmax; v++) {
    double t = cfact(j2+j3+m1-v) * cfact(j1-m1+v)
             / (cfact(v) * cfact(j3-j1+j2-v) * cfact(j3+m3-v) * cfact(v+j1-j2-m3));
    S += (((v + j2 + m2) & 1) != 0) ? -t : t;
  }
  return C * S;
}
struct cx { double re, im; };
__host__ __device__ constexpr cx c2r_ct(int l, int r, int c) {
  int m = r - l;
  double IS2 = 0.70710678118654752440;
  double re = 0.0, im = 0.0;
  if (m < 0) {
    if (c == l - m)      re = IS2;
    else if (c == l + m) im = -IS2;
  } else if (m == 0) {
    if (c == l) re = 1.0;
  } else {
    double s = ((m & 1) != 0) ? -1.0 : 1.0;
    if (c == l + m)      re = s * IS2;
    else if (c == l - m) im = s * IS2;
  }
  double tr = 0.0;
  switch (l & 3) {
    case 1: tr = re; re = im;  im = -tr; break;
    case 2: re = -re; im = -im;          break;
    case 3: tr = re; re = -im; im = tr;  break;
    default: break;
  }
  return cx{re, im};
}
__host__ __device__ constexpr double rcg(int l1,int l2,int l3,int i,int j,int k) {
  double acc = 0.0;
  for (int i2 = 0; i2 < 2*l1+1; i2++)
    for (int k2 = 0; k2 < 2*l2+1; k2++) {
      int m1 = i2 - l1, m2 = k2 - l2, m3 = m1 + m2;
      if (m3 < -l3 || m3 > l3) continue;
      double cc = su2cg_ct(l1, m1, l2, m2, l3, m3);
      if (cc == 0.0) continue;
      cx q1 = c2r_ct(l1, i2, i);
      cx q2 = c2r_ct(l2, k2, j);
      cx q3 = c2r_ct(l3, m3 + l3, k);
      double pr = q1.re*q2.re - q1.im*q2.im;
      double pi = q1.re*q2.im + q1.im*q2.re;
      acc += cc * (pr * q3.re + pi * q3.im);
    }
  return acc;
}
__host__ __device__ constexpr double zclip(double x) {
  return (x > 1e-10 || x < -1e-10) ? x : 0.0;
}

template<int I> struct ic { static constexpr int v = I; };
template<int N, typename F>
__device__ __forceinline__ void sfor(F&& f) {
  if constexpr (N > 0) { sfor<N-1>((F&&)f); f(ic<N-1>{}); }
}

template<int L1,int L2,int L3,bool SYM>
__device__ __forceinline__ void cgc(const float* a, const float* b, float* t) {
  sfor<2*L1+1>([&](auto I) {
    sfor<2*L2+1>([&](auto J) {
      constexpr int iv = decltype(I)::v, jv = decltype(J)::v;
      if constexpr (!SYM || jv >= iv) {
        const float p = a[iv] * b[jv];
        sfor<2*L3+1>([&](auto K) {
          constexpr int kv = decltype(K)::v;
          constexpr float cc =
            (float)zclip(rcg(L1,L2,L3,iv,jv,kv) * ((SYM && iv != jv) ? 2.0 : 1.0));
          if constexpr (cc != 0.f) t[kv] = fmaf(cc, p, t[kv]);
        });
      }
    });
  });
}

// bf16 helpers
__device__ __forceinline__ unsigned bfpack(float lo, float hi) {
  __nv_bfloat162 h = __floats2bfloat162_rn(lo, hi);   // .x = lo half (k even)
  return *(unsigned*)&h;
}
__device__ __forceinline__ float bfhi(float x) {
  return __bfloat162float(__float2bfloat16_rn(x));
}

// ---------------------------------------------------------------------------
// Per-lane product basis (bit-identical to the verified R12/R13 phase A core).
// ---------------------------------------------------------------------------
__device__ __forceinline__ void lane_product(const float* __restrict__ fp,
                                             const float* __restrict__ w1p,
                                             const float* __restrict__ w2p,
                                             const float* __restrict__ w3p,
                                             float* o4) {
#define W1(p) w1p[(p)*NCH]
#define W2(p) w2p[(p)*NCH]
#define W3(p) w3p[(p)*NCH]
  float A[9];
#pragma unroll
  for (int k = 0; k < 9; k++) A[k] = fp[k];
  const float  A0 = A[0];
  const float* A1 = A + 1;
  const float* A2 = A + 4;

  constexpr float c110 = (float)rcg(1,1,0, 0,0,0);
  constexpr float c220 = (float)rcg(2,2,0, 0,0,0);
  constexpr float c111 = (float)rcg(1,1,1, 0,1,2);

  float B0 = W1(0) * A0;
  float B1[3];
#pragma unroll
  for (int k = 0; k < 3; k++) B1[k] = W1(1) * A1[k];

  float t000 = A0 * A0;
  B0 = fmaf(W2(0), t000, B0);
  float S0_00 = W3(0) * t000;
  float S0_11 = W3(1) * t000;

  float d11 = fmaf(A1[2], A1[2], fmaf(A1[1], A1[1], A1[0]*A1[0]));
  float d22 = fmaf(A2[4], A2[4], fmaf(A2[3], A2[3],
               fmaf(A2[2], A2[2], fmaf(A2[1], A2[1], A2[0]*A2[0]))));
  float t110 = c110 * d11;
  B0    = fmaf(W2(3),  t110, B0);
  S0_00 = fmaf(W3(13), t110, S0_00);
  S0_11 = fmaf(W3(14), t110, S0_11);
  float t220 = c220 * d22;
  B0    = fmaf(W2(7),  t220, B0);
  S0_00 = fmaf(W3(41), t220, S0_00);
  S0_11 = fmaf(W3(42), t220, S0_11);

  float S1_01[3], S1_10[3], S1_11[3], S1_21[3];
  {
    float u = (W2(1) + W2(2)) * A0;
#pragma unroll
    for (int k = 0; k < 3; k++) B1[k] = fmaf(u, A1[k], B1[k]);
    float u01 = (W3(2) + W3(9))  * A0;
    float u10 = (W3(3) + W3(10)) * A0;
    float u11 = (W3(4) + W3(11)) * A0;
    float u21 = (W3(5) + W3(12)) * A0;
#pragma unroll
    for (int k = 0; k < 3; k++) {
      S1_01[k] = u01 * A1[k];
      S1_10[k] = u10 * A1[k];
      S1_11[k] = u11 * A1[k];
      S1_21[k] = u21 * A1[k];
    }
  }
  float S2_11[5], S2_20[5], S2_21[5];
  {
    float u11 = (W3(6) + W3(30)) * A0;
    float u20 = (W3(7) + W3(31)) * A0;
    float u21 = (W3(8) + W3(32)) * A0;
#pragma unroll
    for (int k = 0; k < 5; k++) {
      S2_11[k] = u11 * A2[k];
      S2_20[k] = u20 * A2[k];
      S2_21[k] = u21 * A2[k];
    }
  }

  {
    float t[5] = {0,0,0,0,0};
    cgc<1,1,2,true>(A1, A1, t);
    float u11 = W3(19), u20 = W3(20), u21 = W3(21);
#pragma unroll
    for (int k = 0; k < 5; k++) {
      S2_11[k] = fmaf(u11, t[k], S2_11[k]);
      S2_20[k] = fmaf(u20, t[k], S2_20[k]);
      S2_21[k] = fmaf(u21, t[k], S2_21[k]);
    }
  }
  {
    float t[3] = {0,0,0};
    cgc<1,2,1,false>(A1, A2, t);
    float ub  = W2(5)  + W2(6);
    float u01 = W3(22) + W3(33);
    float u10 = W3(23) + W3(34);
    float u11 = W3(24) + W3(35);
    float u21 = W3(25) + W3(36);
#pragma unroll
    for (int k = 0; k < 3; k++) {
      B1[k]    = fmaf(ub,  t[k], B1[k]);
      S1_01[k] = fmaf(u01, t[k], S1_01[k]);
      S1_10[k] = fmaf(u10, t[k], S1_10[k]);
      S1_11[k] = fmaf(u11, t[k], S1_11[k]);
      S1_21[k] = fmaf(u21, t[k], S1_21[k]);
    }
  }
  {
    float t[5] = {0,0,0,0,0};
    cgc<1,2,2,false>(A1, A2, t);
    float u11 = W3(26) - W3(37);
    float u20 = W3(27) - W3(38);
    float u21 = W3(28) - W3(39);
#pragma unroll
    for (int k = 0; k < 5; k++) {
      S2_11[k] = fmaf(u11, t[k], S2_11[k]);
      S2_20[k] = fmaf(u20, t[k], S2_20[k]);
      S2_21[k] = fmaf(u21, t[k], S2_21[k]);
    }
  }
  float S3_21[7];
  {
    float t[7] = {0,0,0,0,0,0,0};
    cgc<1,2,3,false>(A1, A2, t);
    float u = W3(29) + W3(40);
#pragma unroll
    for (int k = 0; k < 7; k++) S3_21[k] = u * t[k];
  }
  {
    float t[5] = {0,0,0,0,0};
    cgc<2,2,2,true>(A2, A2, t);
    float u11 = W3(47), u20 = W3(48), u21 = W3(49);
#pragma unroll
    for (int k = 0; k < 5; k++) {
      S2_11[k] = fmaf(u11, t[k], S2_11[k]);
      S2_20[k] = fmaf(u20, t[k], S2_20[k]);
      S2_21[k] = fmaf(u21, t[k], S2_21[k]);
    }
  }

  B0 = fmaf(S0_00, A0, B0);
#pragma unroll
  for (int k = 0; k < 3; k++) {
    B1[k] = fmaf(S0_11, A1[k], B1[k]);
    B1[k] = fmaf(S1_01[k], A0, B1[k]);
  }
  {
    float d = fmaf(S1_10[2], A1[2], fmaf(S1_10[1], A1[1], S1_10[0]*A1[0]));
    B0 = fmaf(c110, d, B0);
  }
  {
    float cxp = fmaf(-S1_11[2], A1[1], S1_11[1]*A1[2]);
    float cyp = fmaf(-S1_11[0], A1[2], S1_11[2]*A1[0]);
    float czp = fmaf(-S1_11[1], A1[0], S1_11[0]*A1[1]);
    B1[0] = fmaf(c111, cxp, B1[0]);
    B1[1] = fmaf(c111, cyp, B1[1]);
    B1[2] = fmaf(c111, czp, B1[2]);
  }
  cgc<1,2,1,false>(S1_21, A2, B1);
  cgc<2,1,1,false>(S2_11, A1, B1);
  {
    float d = fmaf(S2_20[4], A2[4], fmaf(S2_20[3], A2[3],
               fmaf(S2_20[2], A2[2], fmaf(S2_20[1], A2[1], S2_20[0]*A2[0]))));
    B0 = fmaf(c220, d, B0);
  }
  cgc<2,2,1,false>(S2_21, A2, B1);
  cgc<3,2,1,false>(S3_21, A2, B1);

  o4[0] = B0; o4[1] = B1[0]; o4[2] = B1[1]; o4[3] = B1[2];
#undef W1
#undef W2
#undef W3
}

// ---------------------------------------------------------------------------
// W fragment kernel (exact R12 tail logic, standalone).
// ---------------------------------------------------------------------------
__global__ __launch_bounds__(256)
void wfrag_kernel(const float* __restrict__ lin_w0,
                  const float* __restrict__ lin_w1) {
  int idx = blockIdx.x * 256 + threadIdx.x;    // 0..8191
  int lane = idx & 31;
  int kk   = (idx >> 5) & 7;
  int pair = (idx >> 8) & 7;
  int sp   = (idx >> 11) & 1;
  int wsel = idx >> 12;
  const float* Wsrc = wsel ? lin_w1 : lin_w0;
  int qr = lane >> 2, qc = lane & 3;
  int k0 = kk * 16 + qc * 2;
  int f0 = pair * 16 + qr;
  int f1 = f0 + 8;
  float v[8];
  v[0] = Wsrc[k0 * NFEAT + f0];       v[1] = Wsrc[(k0 + 1) * NFEAT + f0];
  v[2] = Wsrc[(k0 + 8) * NFEAT + f0]; v[3] = Wsrc[(k0 + 9) * NFEAT + f0];
  v[4] = Wsrc[k0 * NFEAT + f1];       v[5] = Wsrc[(k0 + 1) * NFEAT + f1];
  v[6] = Wsrc[(k0 + 8) * NFEAT + f1]; v[7] = Wsrc[(k0 + 9) * NFEAT + f1];
  if (sp) {
#pragma unroll
    for (int i = 0; i < 8; i++) v[i] = v[i] - bfhi(v[i]);
  }
  uint4 o;
  o.x = bfpack(v[0], v[1]);
  o.y = bfpack(v[2], v[3]);
  o.z = bfpack(v[4], v[5]);
  o.w = bfpack(v[6], v[7]);
  g_Wb[(((wsel * 2 + sp) * 8 + pair) * 8 + kk) * 32 + lane] = o;
}

// ---------------------------------------------------------------------------
// Fused kernel: one block = 16 nodes. phaseA math -> s_t -> in-smem fragment
// repack -> bf16 mma (A from smem, B from hot g_Wb) -> coalesced output.
// ---------------------------------------------------------------------------
__device__ __forceinline__ void mma16(float* c, unsigned a0, unsigned a1, unsigned a2,
                                      unsigned a3, unsigned b0, unsigned b1) {
  asm("mma.sync.aligned.m16n8k16.row.col.f32.bf16.bf16.f32 "
      "{%0,%1,%2,%3},{%4,%5,%6,%7},{%8,%9},{%0,%1,%2,%3};"
      : "+f"(c[0]), "+f"(c[1]), "+f"(c[2]), "+f"(c[3])
      : "r"(a0), "r"(a1), "r"(a2), "r"(a3), "r"(b0), "r"(b1));
}

#define SPO 516                       // s_out row pitch (128*4 + 4)
#define SMEM_T_BYTES  (16 * SPO * 4)  // 33024, covers s_t (32768) and s_out
#define SMEM_A_OFF    33280           // 16B-aligned
#define SMEM_TOTAL    (SMEM_A_OFF + 8 * 8 * 32 * 16)   // + 32768 = 66048

__global__ __launch_bounds__(256)
void fused_kernel(const float* __restrict__ feats,
                  const float* __restrict__ w1,
                  const float* __restrict__ w2,
                  const float* __restrict__ w3,
                  const int*   __restrict__ species,
                  float* __restrict__ out) {
  extern __shared__ char smem[];
  float* s_t   = (float*)smem;                       // [nl][c][m] fp32
  float* s_out = (float*)smem;                       // aliases s_t (after repack)
  uint4* s_A   = (uint4*)(smem + SMEM_A_OFF);        // [(sp*4+m)*8+kk][lane]

  const int tid   = threadIdx.x;
  const int nbase = blockIdx.x * 16;

  // ---- phase A: 8 lanes per thread ----
#pragma unroll 1
  for (int r = 0; r < 8; r++) {
    int L  = tid + r * 256;
    int nl = L >> 7, c = L & 127;
    int n  = nbase + nl;
    int e  = species[n];
    const float* fp = feats + ((size_t)n * NCH + c) * 9;
    float o4[4];
    lane_product(fp,
                 w1 + (size_t)(e * 2)  * NCH + c,
                 w2 + (size_t)(e * 9)  * NCH + c,
                 w3 + (size_t)(e * 51) * NCH + c, o4);
    *(float4*)&s_t[(nl * 128 + c) * 4] = make_float4(o4[0], o4[1], o4[2], o4[3]);
  }
  __syncthreads();

  // ---- repack to bf16-split fragments in smem (R12 index math, nl in-block) ----
#pragma unroll
  for (int r = 0; r < 16; r++) {
    int w  = tid + r * 256;            // 0..4095
    int qc = w & 3;
    int m  = (w >> 2) & 3;
    int kk = (w >> 4) & 7;
    int sp = (w >> 7) & 1;
    int nl = w >> 8;                   // 0..15
    int k0 = kk * 16 + qc * 2;
    float vE0 = s_t[(nl * 128 + k0) * 4 + m],     vE1 = s_t[(nl * 128 + k0 + 1) * 4 + m];
    float vF0 = s_t[(nl * 128 + k0 + 8) * 4 + m], vF1 = s_t[(nl * 128 + k0 + 9) * 4 + m];
    unsigned pE, pF;
    if (sp == 0) {
      pE = bfpack(vE0, vE1);
      pF = bfpack(vF0, vF1);
    } else {
      pE = bfpack(vE0 - bfhi(vE0), vE1 - bfhi(vE1));
      pF = bfpack(vF0 - bfhi(vF0), vF1 - bfhi(vF1));
    }
    int qr   = nl & 7;
    int lane = qr * 4 + qc;
    int comp = (nl < 8) ? 0 : 1;
    unsigned* base = (unsigned*)&s_A[((sp * 4 + m) * 8 + kk) * 32 + lane];
    base[comp]     = pE;   // a0 / a1
    base[comp + 2] = pF;   // a2 / a3
  }
  __syncthreads();

  // ---- mma: warp w -> m = w>>1, f-half = (w&1)*64 (8 tiles = 4 pairs) ----
  const int warp = tid >> 5, lane = tid & 31;
  const int m    = warp >> 1;
  const int fsub = warp & 1;
  const int wsel = (m == 0) ? 0 : 1;

  const uint4* BhB = g_Wb + (((wsel * 2 + 0) * 8 + fsub * 4) * 8) * 32 + lane;
  const uint4* BlB = g_Wb + (((wsel * 2 + 1) * 8 + fsub * 4) * 8) * 32 + lane;

  float acc[8][4];
#pragma unroll
  for (int t = 0; t < 8; t++)
#pragma unroll
    for (int k = 0; k < 4; k++) acc[t][k] = 0.f;

#pragma unroll
  for (int kk = 0; kk < 8; kk++) {
    uint4 aH = s_A[(m * 8 + kk) * 32 + lane];
    uint4 aL = s_A[((4 + m) * 8 + kk) * 32 + lane];
#pragma unroll
    for (int pr = 0; pr < 4; pr++) {
      uint4 bH = BhB[pr * 256 + kk * 32];
      uint4 bL = BlB[pr * 256 + kk * 32];
      float* a0 = acc[pr * 2];
      float* a1 = acc[pr * 2 + 1];
      mma16(a0, aH.x, aH.y, aH.z, aH.w, bH.x, bH.y);
      mma16(a0, aH.x, aH.y, aH.z, aH.w, bL.x, bL.y);
      mma16(a0, aL.x, aL.y, aL.z, aL.w, bH.x, bH.y);
      mma16(a1, aH.x, aH.y, aH.z, aH.w, bH.z, bH.w);
      mma16(a1, aH.x, aH.y, aH.z, aH.w, bL.z, bL.w);
      mma16(a1, aL.x, aL.y, aL.z, aL.w, bH.z, bH.w);
    }
  }

  // ---- epilogue: stage [nl][f][m] into s_out (aliases s_t; safe post-repack) ----
  const int qr = lane >> 2;
  const int qc = lane & 3;
#pragma unroll
  for (int t = 0; t < 8; t++) {
    int fl = (fsub * 8 + t) * 8 + qc * 2;
    int r0 = qr * SPO;
    int r8 = (qr + 8) * SPO;
    s_out[r0 + fl * 4 + m]       = acc[t][0];
    s_out[r0 + (fl + 1) * 4 + m] = acc[t][1];
    s_out[r8 + fl * 4 + m]       = acc[t][2];
    s_out[r8 + (fl + 1) * 4 + m] = acc[t][3];
  }
  __syncthreads();

  const float s = 0.08838834764831845f;  // 1/sqrt(128)
  float4* op = (float4*)out;
#pragma unroll
  for (int i = 0; i < 8; i++) {
    int idx = tid + i * 256;           // 0..2047 over 16n x 128f
    int nl = idx >> 7, fl = idx & 127;
    float4 v = *(const float4*)&s_out[nl * SPO + fl * 4];
    v.x *= s; v.y *= s; v.z *= s; v.w *= s;
    op[(size_t)(nbase + nl) * NFEAT + fl] = v;
  }
}

// ---------------------------------------------------------------------------
// Launch
// ---------------------------------------------------------------------------
extern "C" void kernel_launch(void* const* d_in, const int* in_sizes, int n_in,
                              void* d_out, int out_size) {
  const float* feats   = (const float*)d_in[0];  // [4096,128,9]
  const float* w1      = (const float*)d_in[1];  // [10,2,128]
  const float* w2      = (const float*)d_in[2];  // [10,9,128]
  const float* w3      = (const float*)d_in[3];  // [10,51,128]
  const float* lin_w0  = (const float*)d_in[4];  // [128,128]
  const float* lin_w1  = (const float*)d_in[5];  // [128,128]
  const int*   species = (const int*)d_in[6];    // [4096]

  cudaFuncSetAttribute(fused_kernel,
                       cudaFuncAttributeMaxDynamicSharedMemorySize, SMEM_TOTAL);
  wfrag_kernel<<<32, 256>>>(lin_w0, lin_w1);
  fused_kernel<<<NN16, 256, SMEM_TOTAL>>>(feats, w1, w2, w3, species, (float*)d_out);
}

// round 16
// speedup vs baseline: 1.1547x; 1.1547x over previous
#include <cuda_runtime.h>
#include <cuda_bf16.h>
#include <math.h>

#define NNODES 4096
#define NCH    128
#define NELEM  10
#define NFEAT  128
#define NN16   (NNODES / 16)   // 256

// BF16 2-way-split fragment storage for phase B (mma.m16n8k16 bf16):
//  g_Xa[sp][m][n16][kk16][lane] = uint4 {a0,a1,a2,a3} (bf16x2 each)
//  g_Wb[wsel][sp][pair][kk16][lane] = uint4 {b0_t,b1_t,b0_t',b1_t'}
__device__ uint4 g_Xa[2 * 4 * NN16 * 8 * 32];   // 8 MB
__device__ uint4 g_Wb[2 * 2 * 8 * 8 * 32];      // 128 KB

// ===========================================================================
// Compile-time real Clebsch-Gordan coefficients (e3nn convention).
// ===========================================================================
__host__ __device__ constexpr double cfact(int n) {
  double r = 1.0;
  for (int i = 2; i <= n; i++) r *= (double)i;
  return r;
}
__host__ __device__ constexpr double csqrt(double x) {
  if (x <= 0.0) return 0.0;
  double g = x > 1.0 ? x : 1.0;
  for (int i = 0; i < 64; i++) g = 0.5 * (g + x / g);
  return g;
}
__host__ __device__ constexpr double su2cg_ct(int j1,int m1,int j2,int m2,int j3,int m3) {
  if (m1 + m2 != m3) return 0.0;
  int vmin = -j1 + j2 + m3; if (-j1 + m1 > vmin) vmin = -j1 + m1; if (0 > vmin) vmin = 0;
  int vmax = j2 + j3 + m1; if (j3 - j1 + j2 < vmax) vmax = j3 - j1 + j2; if (j3 + m3 < vmax) vmax = j3 + m3;
  if (vmax < vmin) return 0.0;
  double C = csqrt((2.0*j3 + 1.0) * cfact(j3+j1-j2) * cfact(j3-j1+j2) * cfact(j1+j2-j3)
                   * cfact(j3+m3) * cfact(j3-m3)
                   / (cfact(j1+j2+j3+1) * cfact(j1-m1) * cfact(j1+m1)
                      * cfact(j2-m2) * cfact(j2+m2)));
  double S = 0.0;
  for (int v = vmin; v <= vmax; v++) {
    double t = cfact(j2+j3+m1-v) * cfact(j1-m1+v)
             / (cfact(v) * cfact(j3-j1+j2-v) * cfact(j3+m3-v) * cfact(v+j1-j2-m3));
    S += (((v + j2 + m2) & 1) != 0) ? -t : t;
  }
  return C * S;
}
struct cx { double re, im; };
__host__ __device__ constexpr cx c2r_ct(int l, int r, int c) {
  int m = r - l;
  double IS2 = 0.70710678118654752440;
  double re = 0.0, im = 0.0;
  if (m < 0) {
    if (c == l - m)      re = IS2;
    else if (c == l + m) im = -IS2;
  } else if (m == 0) {
    if (c == l) re = 1.0;
  } else {
    double s = ((m & 1) != 0) ? -1.0 : 1.0;
    if (c == l + m)      re = s * IS2;
    else if (c == l - m) im = s * IS2;
  }
  double tr = 0.0;
  switch (l & 3) {
    case 1: tr = re; re = im;  im = -tr; break;
    case 2: re = -re; im = -im;          break;
    case 3: tr = re; re = -im; im = tr;  break;
    default: break;
  }
  return cx{re, im};
}
__host__ __device__ constexpr double rcg(int l1,int l2,int l3,int i,int j,int k) {
  double acc = 0.0;
  for (int i2 = 0; i2 < 2*l1+1; i2++)
    for (int k2 = 0; k2 < 2*l2+1; k2++) {
      int m1 = i2 - l1, m2 = k2 - l2, m3 = m1 + m2;
      if (m3 < -l3 || m3 > l3) continue;
      double cc = su2cg_ct(l1, m1, l2, m2, l3, m3);
      if (cc == 0.0) continue;
      cx q1 = c2r_ct(l1, i2, i);
      cx q2 = c2r_ct(l2, k2, j);
      cx q3 = c2r_ct(l3, m3 + l3, k);
      double pr = q1.re*q2.re - q1.im*q2.im;
      double pi = q1.re*q2.im + q1.im*q2.re;
      acc += cc * (pr * q3.re + pi * q3.im);
    }
  return acc;
}
__host__ __device__ constexpr double zclip(double x) {
  return (x > 1e-10 || x < -1e-10) ? x : 0.0;
}

template<int I> struct ic { static constexpr int v = I; };
template<int N, typename F>
__device__ __forceinline__ void sfor(F&& f) {
  if constexpr (N > 0) { sfor<N-1>((F&&)f); f(ic<N-1>{}); }
}

template<int L1,int L2,int L3,bool SYM>
__device__ __forceinline__ void cgc(const float* a, const float* b, float* t) {
  sfor<2*L1+1>([&](auto I) {
    sfor<2*L2+1>([&](auto J) {
      constexpr int iv = decltype(I)::v, jv = decltype(J)::v;
      if constexpr (!SYM || jv >= iv) {
        const float p = a[iv] * b[jv];
        sfor<2*L3+1>([&](auto K) {
          constexpr int kv = decltype(K)::v;
          constexpr float cc =
            (float)zclip(rcg(L1,L2,L3,iv,jv,kv) * ((SYM && iv != jv) ? 2.0 : 1.0));
          if constexpr (cc != 0.f) t[kv] = fmaf(cc, p, t[kv]);
        });
      }
    });
  });
}

// bf16 helpers
__device__ __forceinline__ unsigned bfpack(float lo, float hi) {
  __nv_bfloat162 h = __floats2bfloat162_rn(lo, hi);   // .x = lo half (k even)
  return *(unsigned*)&h;
}
__device__ __forceinline__ float bfhi(float x) {
  return __bfloat162float(__float2bfloat16_rn(x));
}

// ---------------------------------------------------------------------------
// Phase A — R12/R13 math (known good), with min-3-blocks occupancy hint.
// bf16-split fragment repack epilogue, W fragment tail.
// ---------------------------------------------------------------------------
__global__ __launch_bounds__(256, 3)
void phaseA_kernel(const float* __restrict__ feats,
                   const float* __restrict__ w1,
                   const float* __restrict__ w2,
                   const float* __restrict__ w3,
                   const int*   __restrict__ species,
                   const float* __restrict__ lin_w0,
                   const float* __restrict__ lin_w1) {
  __shared__ float s_t[2][128][4];

  const int c = threadIdx.x & 127;
  const int nl_self = threadIdx.x >> 7;
  const int n = blockIdx.x * 2 + nl_self;

  const int e = species[n];
  const float* fp = feats + ((size_t)n * NCH + c) * 9;
  float A[9];
#pragma unroll
  for (int k = 0; k < 9; k++) A[k] = fp[k];
  const float  A0 = A[0];
  const float* A1 = A + 1;
  const float* A2 = A + 4;

  const float* w1p = w1 + (size_t)(e * 2)  * NCH + c;
  const float* w2p = w2 + (size_t)(e * 9)  * NCH + c;
  const float* w3p = w3 + (size_t)(e * 51) * NCH + c;
#define W1(p) w1p[(p)*NCH]
#define W2(p) w2p[(p)*NCH]
#define W3(p) w3p[(p)*NCH]

  constexpr float c110 = (float)rcg(1,1,0, 0,0,0);
  constexpr float c220 = (float)rcg(2,2,0, 0,0,0);
  constexpr float c111 = (float)rcg(1,1,1, 0,1,2);

  float B0 = W1(0) * A0;
  float B1[3];
#pragma unroll
  for (int k = 0; k < 3; k++) B1[k] = W1(1) * A1[k];

  float t000 = A0 * A0;
  B0 = fmaf(W2(0), t000, B0);
  float S0_00 = W3(0) * t000;
  float S0_11 = W3(1) * t000;

  float d11 = fmaf(A1[2], A1[2], fmaf(A1[1], A1[1], A1[0]*A1[0]));
  float d22 = fmaf(A2[4], A2[4], fmaf(A2[3], A2[3],
               fmaf(A2[2], A2[2], fmaf(A2[1], A2[1], A2[0]*A2[0]))));
  float t110 = c110 * d11;
  B0    = fmaf(W2(3),  t110, B0);
  S0_00 = fmaf(W3(13), t110, S0_00);
  S0_11 = fmaf(W3(14), t110, S0_11);
  float t220 = c220 * d22;
  B0    = fmaf(W2(7),  t220, B0);
  S0_00 = fmaf(W3(41), t220, S0_00);
  S0_11 = fmaf(W3(42), t220, S0_11);

  float S1_01[3], S1_10[3], S1_11[3], S1_21[3];
  {
    float u = (W2(1) + W2(2)) * A0;
#pragma unroll
    for (int k = 0; k < 3; k++) B1[k] = fmaf(u, A1[k], B1[k]);
    float u01 = (W3(2) + W3(9))  * A0;
    float u10 = (W3(3) + W3(10)) * A0;
    float u11 = (W3(4) + W3(11)) * A0;
    float u21 = (W3(5) + W3(12)) * A0;
#pragma unroll
    for (int k = 0; k < 3; k++) {
      S1_01[k] = u01 * A1[k];
      S1_10[k] = u10 * A1[k];
      S1_11[k] = u11 * A1[k];
      S1_21[k] = u21 * A1[k];
    }
  }
  float S2_11[5], S2_20[5], S2_21[5];
  {
    float u11 = (W3(6) + W3(30)) * A0;
    float u20 = (W3(7) + W3(31)) * A0;
    float u21 = (W3(8) + W3(32)) * A0;
#pragma unroll
    for (int k = 0; k < 5; k++) {
      S2_11[k] = u11 * A2[k];
      S2_20[k] = u20 * A2[k];
      S2_21[k] = u21 * A2[k];
    }
  }

  {
    float t[5] = {0,0,0,0,0};
    cgc<1,1,2,true>(A1, A1, t);
    float u11 = W3(19), u20 = W3(20), u21 = W3(21);
#pragma unroll
    for (int k = 0; k < 5; k++) {
      S2_11[k] = fmaf(u11, t[k], S2_11[k]);
      S2_20[k] = fmaf(u20, t[k], S2_20[k]);
      S2_21[k] = fmaf(u21, t[k], S2_21[k]);
    }
  }
  {
    float t[3] = {0,0,0};
    cgc<1,2,1,false>(A1, A2, t);
    float ub  = W2(5)  + W2(6);
    float u01 = W3(22) + W3(33);
    float u10 = W3(23) + W3(34);
    float u11 = W3(24) + W3(35);
    float u21 = W3(25) + W3(36);
#pragma unroll
    for (int k = 0; k < 3; k++) {
      B1[k]    = fmaf(ub,  t[k], B1[k]);
      S1_01[k] = fmaf(u01, t[k], S1_01[k]);
      S1_10[k] = fmaf(u10, t[k], S1_10[k]);
      S1_11[k] = fmaf(u11, t[k], S1_11[k]);
      S1_21[k] = fmaf(u21, t[k], S1_21[k]);
    }
  }
  {
    float t[5] = {0,0,0,0,0};
    cgc<1,2,2,false>(A1, A2, t);
    float u11 = W3(26) - W3(37);
    float u20 = W3(27) - W3(38);
    float u21 = W3(28) - W3(39);
#pragma unroll
    for (int k = 0; k < 5; k++) {
      S2_11[k] = fmaf(u11, t[k], S2_11[k]);
      S2_20[k] = fmaf(u20, t[k], S2_20[k]);
      S2_21[k] = fmaf(u21, t[k], S2_21[k]);
    }
  }
  float S3_21[7];
  {
    float t[7] = {0,0,0,0,0,0,0};
    cgc<1,2,3,false>(A1, A2, t);
    float u = W3(29) + W3(40);
#pragma unroll
    for (int k = 0; k < 7; k++) S3_21[k] = u * t[k];
  }
  {
    float t[5] = {0,0,0,0,0};
    cgc<2,2,2,true>(A2, A2, t);
    float u11 = W3(47), u20 = W3(48), u21 = W3(49);
#pragma unroll
    for (int k = 0; k < 5; k++) {
      S2_11[k] = fmaf(u11, t[k], S2_11[k]);
      S2_20[k] = fmaf(u20, t[k], S2_20[k]);
      S2_21[k] = fmaf(u21, t[k], S2_21[k]);
    }
  }

  B0 = fmaf(S0_00, A0, B0);
#pragma unroll
  for (int k = 0; k < 3; k++) {
    B1[k] = fmaf(S0_11, A1[k], B1[k]);
    B1[k] = fmaf(S1_01[k], A0, B1[k]);
  }
  {
    float d = fmaf(S1_10[2], A1[2], fmaf(S1_10[1], A1[1], S1_10[0]*A1[0]));
    B0 = fmaf(c110, d, B0);
  }
  {
    float cxp = fmaf(-S1_11[2], A1[1], S1_11[1]*A1[2]);
    float cyp = fmaf(-S1_11[0], A1[2], S1_11[2]*A1[0]);
    float czp = fmaf(-S1_11[1], A1[0], S1_11[0]*A1[1]);
    B1[0] = fmaf(c111, cxp, B1[0]);
    B1[1] = fmaf(c111, cyp, B1[1]);
    B1[2] = fmaf(c111, czp, B1[2]);
  }
  cgc<1,2,1,false>(S1_21, A2, B1);
  cgc<2,1,1,false>(S2_11, A1, B1);
  {
    float d = fmaf(S2_20[4], A2[4], fmaf(S2_20[3], A2[3],
               fmaf(S2_20[2], A2[2], fmaf(S2_20[1], A2[1], S2_20[0]*A2[0]))));
    B0 = fmaf(c220, d, B0);
  }
  cgc<2,2,1,false>(S2_21, A2, B1);
  cgc<3,2,1,false>(S3_21, A2, B1);

  // ---- fragment repack: smem transpose, bf16 2-split, component stores ----
  *(float4*)&s_t[nl_self][c][0] = make_float4(B0, B1[0], B1[1], B1[2]);
  __syncthreads();
  {
    const int n0 = blockIdx.x * 2;
    const int n16 = n0 >> 4;
#pragma unroll
    for (int r = 0; r < 2; r++) {
      int w  = threadIdx.x + r * 256;            // 0..511
      int qc = w & 3;
      int m  = (w >> 2) & 3;
      int kk = (w >> 4) & 7;
      int sp = (w >> 7) & 1;
      int nl = w >> 8;
      int nn = n0 + nl;
      int k0 = kk * 16 + qc * 2;
      float vE0 = s_t[nl][k0][m],     vE1 = s_t[nl][k0 + 1][m];
      float vF0 = s_t[nl][k0 + 8][m], vF1 = s_t[nl][k0 + 9][m];
      unsigned pE, pF;
      if (sp == 0) {
        pE = bfpack(vE0, vE1);
        pF = bfpack(vF0, vF1);
      } else {
        pE = bfpack(vE0 - bfhi(vE0), vE1 - bfhi(vE1));
        pF = bfpack(vF0 - bfhi(vF0), vF1 - bfhi(vF1));
      }
      int qr = nn & 7;
      int lane = qr * 4 + qc;
      int comp = ((nn & 15) < 8) ? 0 : 1;
      unsigned* base =
        (unsigned*)&g_Xa[((((sp * 4 + m) * NN16 + n16) * 8) + kk) * 32 + lane];
      base[comp]     = pE;   // a0 / a1
      base[comp + 2] = pF;   // a2 / a3
    }
  }

  // ---- W fragment tail (blocks 0..31, one uint4/thread) ----
  if (blockIdx.x < 32) {
    int idx = blockIdx.x * 256 + threadIdx.x;    // 0..8191
    int lane = idx & 31;
    int kk   = (idx >> 5) & 7;
    int pair = (idx >> 8) & 7;
    int sp   = (idx >> 11) & 1;
    int wsel = idx >> 12;
    const float* Wsrc = wsel ? lin_w1 : lin_w0;
    int qr = lane >> 2, qc = lane & 3;
    int k0 = kk * 16 + qc * 2;
    int f0 = pair * 16 + qr;
    int f1 = f0 + 8;
    float v[8];
    v[0] = Wsrc[k0 * NFEAT + f0];       v[1] = Wsrc[(k0 + 1) * NFEAT + f0];
    v[2] = Wsrc[(k0 + 8) * NFEAT + f0]; v[3] = Wsrc[(k0 + 9) * NFEAT + f0];
    v[4] = Wsrc[k0 * NFEAT + f1];       v[5] = Wsrc[(k0 + 1) * NFEAT + f1];
    v[6] = Wsrc[(k0 + 8) * NFEAT + f1]; v[7] = Wsrc[(k0 + 9) * NFEAT + f1];
    if (sp) {
#pragma unroll
      for (int i = 0; i < 8; i++) v[i] = v[i] - bfhi(v[i]);
    }
    uint4 o;
    o.x = bfpack(v[0], v[1]);  // b0 tcol 2p
    o.y = bfpack(v[2], v[3]);  // b1 tcol 2p
    o.z = bfpack(v[4], v[5]);  // b0 tcol 2p+1
    o.w = bfpack(v[6], v[7]);  // b1 tcol 2p+1
    g_Wb[(((wsel * 2 + sp) * 8 + pair) * 8 + kk) * 32 + lane] = o;
  }
#undef W1
#undef W2
#undef W3
}

// ---------------------------------------------------------------------------
// Phase B — EXACT R14 version (best known): A tile burst-staged into smem,
// B on the global prefetch path, m16n8k16 bf16 2-split mma.
// ---------------------------------------------------------------------------
__device__ __forceinline__ void mma16(float* c, unsigned a0, unsigned a1, unsigned a2,
                                      unsigned a3, unsigned b0, unsigned b1) {
  asm("mma.sync.aligned.m16n8k16.row.col.f32.bf16.bf16.f32 "
      "{%0,%1,%2,%3},{%4,%5,%6,%7},{%8,%9},{%0,%1,%2,%3};"
      : "+f"(c[0]), "+f"(c[1]), "+f"(c[2]), "+f"(c[3])
      : "r"(a0), "r"(a1), "r"(a2), "r"(a3), "r"(b0), "r"(b1));
}

#define SPB 132   // s_out row pitch in floats (32*4 + 4 pad)

__global__ __launch_bounds__(256)
void phaseB_kernel(float* __restrict__ out) {
  __shared__ uint4 s_A[8][8][32];     // [sp*4+m][kk][lane], 32 KB
  __shared__ float s_out[16 * SPB];   // ~8.4 KB

  const int tid  = threadIdx.x;
  const int warp = tid >> 5, lane = tid & 31;
  const int n16  = blockIdx.x >> 2;
  const int fblk = blockIdx.x & 3;

  // burst-stage A tile: warp w loads chunk (sp*4+m) = w, 8 coalesced LDG.128
  {
    const uint4* src = g_Xa + ((size_t)warp * NN16 + n16) * 256 + lane;
#pragma unroll
    for (int kk = 0; kk < 8; kk++)
      s_A[warp][kk][lane] = src[kk * 32];
  }

  const int m    = warp >> 1;
  const int fsub = warp & 1;
  const int pair = fblk * 2 + fsub;
  const int wsel = (m == 0) ? 0 : 1;
  const uint4* Bh = g_Wb + (((wsel * 2 + 0) * 8 + pair) * 8) * 32 + lane;
  const uint4* Bl = g_Wb + (((wsel * 2 + 1) * 8 + pair) * 8) * 32 + lane;

  float acc[2][4];
#pragma unroll
  for (int t = 0; t < 2; t++)
#pragma unroll
    for (int k = 0; k < 4; k++) acc[t][k] = 0.f;

  // B prefetch can start before the sync (global, independent of s_A)
  uint4 bH = Bh[0], bL = Bl[0];
  __syncthreads();

#pragma unroll
  for (int kk = 0; kk < 8; kk++) {
    uint4 nbH, nbL;
    if (kk < 7) {
      nbH = Bh[(kk + 1) * 32];
      nbL = Bl[(kk + 1) * 32];
    }
    uint4 aH = s_A[m][kk][lane];
    uint4 aL = s_A[4 + m][kk][lane];
    // tile 0 (tcol 2p):  hh, hl, lh
    mma16(acc[0], aH.x, aH.y, aH.z, aH.w, bH.x, bH.y);
    mma16(acc[0], aH.x, aH.y, aH.z, aH.w, bL.x, bL.y);
    mma16(acc[0], aL.x, aL.y, aL.z, aL.w, bH.x, bH.y);
    // tile 1 (tcol 2p+1)
    mma16(acc[1], aH.x, aH.y, aH.z, aH.w, bH.z, bH.w);
    mma16(acc[1], aH.x, aH.y, aH.z, aH.w, bL.z, bL.w);
    mma16(acc[1], aL.x, aL.y, aL.z, aL.w, bH.z, bH.w);
    if (kk < 7) { bH = nbH; bL = nbL; }
  }

  __syncthreads();
  const int qr = lane >> 2;
  const int qc = lane & 3;
#pragma unroll
  for (int t = 0; t < 2; t++) {
    int fl = fsub * 16 + t * 8 + qc * 2;
    int r0 = qr * SPB;
    int r8 = (qr + 8) * SPB;
    s_out[r0 + fl * 4 + m]       = acc[t][0];
    s_out[r0 + (fl + 1) * 4 + m] = acc[t][1];
    s_out[r8 + fl * 4 + m]       = acc[t][2];
    s_out[r8 + (fl + 1) * 4 + m] = acc[t][3];
  }
  __syncthreads();

  const float s = 0.08838834764831845f;  // 1/sqrt(128)
  const int nbase = n16 * 16;
  const int fbase = fblk * 32;
  float4* op = (float4*)out;
#pragma unroll
  for (int i = 0; i < 2; i++) {
    int idx = tid + i * 256;           // 0..511 over 16n x 32f
    int nl = idx >> 5, fl = idx & 31;
    float4 v = *(const float4*)&s_out[nl * SPB + fl * 4];
    v.x *= s; v.y *= s; v.z *= s; v.w *= s;
    op[(size_t)(nbase + nl) * NFEAT + fbase + fl] = v;
  }
}

// ---------------------------------------------------------------------------
// Launch
// ---------------------------------------------------------------------------
extern "C" void kernel_launch(void* const* d_in, const int* in_sizes, int n_in,
                              void* d_out, int out_size) {
  const float* feats   = (const float*)d_in[0];  // [4096,128,9]
  const float* w1      = (const float*)d_in[1];  // [10,2,128]
  const float* w2      = (const float*)d_in[2];  // [10,9,128]
  const float* w3      = (const float*)d_in[3];  // [10,51,128]
  const float* lin_w0  = (const float*)d_in[4];  // [128,128]
  const float* lin_w1  = (const float*)d_in[5];  // [128,128]
  const int*   species = (const int*)d_in[6];    // [4096]

  phaseA_kernel<<<NNODES / 2, 256>>>(feats, w1, w2, w3, species, lin_w0, lin_w1);
  phaseB_kernel<<<NN16 * 4, 256>>>((float*)d_out);
}